// round 6
// baseline (speedup 1.0000x reference)
#include <cuda_runtime.h>
#include <cuda_bf16.h>
#include <math.h>
#include <stdint.h>

#define NNODE 50000
#define DDIM  256
#define HH    8
#define EE    500000
#define QKVW  768
#define ATT_SCALE 0.17677669529663687f  // 1/sqrt(32)

// ======================= device scratch ==========================================
__device__ float g_bcat[2][QKVW];
__device__ __nv_bfloat16 g_WcatT_hi[2][(size_t)QKVW * DDIM];  // [n][k], n = Q|K'|V'
__device__ __nv_bfloat16 g_WcatT_lo[2][(size_t)QKVW * DDIM];
__device__ __nv_bfloat16 g_WaT_hi[2][(size_t)DDIM * DDIM];
__device__ __nv_bfloat16 g_WaT_lo[2][(size_t)DDIM * DDIM];
__device__ __nv_bfloat16 g_fbf_hi[2][(size_t)NNODE * DDIM];
__device__ __nv_bfloat16 g_fbf_lo[2][(size_t)NNODE * DDIM];
__device__ __nv_bfloat16 g_hbf_hi[2][(size_t)NNODE * DDIM];
__device__ __nv_bfloat16 g_hbf_lo[2][(size_t)NNODE * DDIM];
__device__ float g_QKV[2][(size_t)NNODE * QKVW];  // fp32: Q(256)|K'(256)|V'(256)
__device__ float g_trans[2][(size_t)NNODE * DDIM];
// CSR-by-destination scratch
__device__ int g_deg[2][NNODE];
__device__ int g_rows[2][NNODE + 1];
__device__ int g_cursor[2][NNODE];
__device__ int g_esrc[2][EE];

// ======================= PTX helpers (base-target safe) ==========================
__device__ __forceinline__ uint32_t smem_u32(const void* p) {
    uint32_t a;
    asm("{ .reg .u64 t; cvta.to.shared.u64 t, %1; cvt.u32.u64 %0, t; }" : "=r"(a) : "l"(p));
    return a;
}
__device__ __forceinline__ void ldm_x4(uint32_t* r, uint32_t addr) {
    asm volatile("ldmatrix.sync.aligned.m8n8.x4.shared.b16 {%0,%1,%2,%3}, [%4];"
                 : "=r"(r[0]), "=r"(r[1]), "=r"(r[2]), "=r"(r[3]) : "r"(addr));
}
__device__ __forceinline__ void ldm_x2(uint32_t* r, uint32_t addr) {
    asm volatile("ldmatrix.sync.aligned.m8n8.x2.shared.b16 {%0,%1}, [%2];"
                 : "=r"(r[0]), "=r"(r[1]) : "r"(addr));
}
__device__ __forceinline__ void mma_bf16(float* c, const uint32_t* a, const uint32_t* b) {
    asm volatile("mma.sync.aligned.m16n8k16.row.col.f32.bf16.bf16.f32 "
                 "{%0,%1,%2,%3}, {%4,%5,%6,%7}, {%8,%9}, {%0,%1,%2,%3};"
                 : "+f"(c[0]), "+f"(c[1]), "+f"(c[2]), "+f"(c[3])
                 : "r"(a[0]), "r"(a[1]), "r"(a[2]), "r"(a[3]), "r"(b[0]), "r"(b[1]));
}

// ======================= 1. prep: fold + transpose + bf16 split ==================
__global__ __launch_bounds__(256) void prep_kernel(
    const float* __restrict__ Wk, const float* __restrict__ bk,
    const float* __restrict__ Wq, const float* __restrict__ bq,
    const float* __restrict__ Wv, const float* __restrict__ bv,
    const float* __restrict__ Wa,
    const float* __restrict__ w_att, const float* __restrict__ w_msg)
{
    const int t = blockIdx.y;
    const int n = blockIdx.x;
    const int k = threadIdx.x;

    float val;
    if (n < 768) {
        if (n < 256) {
            val = Wq[((size_t)t * 256 + k) * 256 + n];
        } else {
            const int j = (n - 256) & 255;
            const int h = j >> 5, jj = j & 31;
            const float* W = (n < 512) ? Wk : Wv;
            const float* wm = ((n < 512) ? w_att : w_msg) + ((size_t)(t * 8 + h)) * 1024 + jj;
            const float* wrow = W + ((size_t)t * 256 + k) * 256 + h * 32;
            float a = 0.f;
            #pragma unroll 8
            for (int i = 0; i < 32; ++i) a += wrow[i] * wm[i * 32];
            val = a;
        }
        __nv_bfloat16 hi = __float2bfloat16(val);
        __nv_bfloat16 lo = __float2bfloat16(val - __bfloat162float(hi));
        g_WcatT_hi[t][(size_t)n * 256 + k] = hi;
        g_WcatT_lo[t][(size_t)n * 256 + k] = lo;
        if (k == 0) {
            float b;
            if (n < 256) b = bq[t * 256 + n];
            else {
                const int j = (n - 256) & 255;
                const int h = j >> 5, jj = j & 31;
                const float* bb = (n < 512) ? bk : bv;
                const float* wm = ((n < 512) ? w_att : w_msg) + ((size_t)(t * 8 + h)) * 1024 + jj;
                float a = 0.f;
                #pragma unroll 8
                for (int i = 0; i < 32; ++i) a += bb[t * 256 + h * 32 + i] * wm[i * 32];
                b = a;
            }
            g_bcat[t][n] = b;
        }
    } else {
        const int nn = n - 768;
        val = Wa[((size_t)t * 256 + k) * 256 + nn];
        __nv_bfloat16 hi = __float2bfloat16(val);
        __nv_bfloat16 lo = __float2bfloat16(val - __bfloat162float(hi));
        g_WaT_hi[t][(size_t)nn * 256 + k] = hi;
        g_WaT_lo[t][(size_t)nn * 256 + k] = lo;
    }
}

// ======================= 2. fp32 -> bf16 hi/lo split =============================
__global__ void convsplit_kernel(const float* __restrict__ src,
                                 __nv_bfloat16* __restrict__ hi,
                                 __nv_bfloat16* __restrict__ lo, long n4)
{
    long i = (long)blockIdx.x * blockDim.x + threadIdx.x;
    if (i >= n4) return;
    float4 v = ((const float4*)src)[i];
    __nv_bfloat16 h0 = __float2bfloat16(v.x), h1 = __float2bfloat16(v.y);
    __nv_bfloat16 h2 = __float2bfloat16(v.z), h3 = __float2bfloat16(v.w);
    __nv_bfloat16 l0 = __float2bfloat16(v.x - __bfloat162float(h0));
    __nv_bfloat16 l1 = __float2bfloat16(v.y - __bfloat162float(h1));
    __nv_bfloat16 l2 = __float2bfloat16(v.z - __bfloat162float(h2));
    __nv_bfloat16 l3 = __float2bfloat16(v.w - __bfloat162float(h3));
    ((__nv_bfloat162*)hi)[i * 2]     = __halves2bfloat162(h0, h1);
    ((__nv_bfloat162*)hi)[i * 2 + 1] = __halves2bfloat162(h2, h3);
    ((__nv_bfloat162*)lo)[i * 2]     = __halves2bfloat162(l0, l1);
    ((__nv_bfloat162*)lo)[i * 2 + 1] = __halves2bfloat162(l2, l3);
}

// ======================= 3. CSR build ============================================
__global__ void zerodeg_kernel()
{
    int i = blockIdx.x * blockDim.x + threadIdx.x;
    if (i < 2 * NNODE) ((int*)g_deg)[i] = 0;
}

__global__ void hist_kernel(const int* __restrict__ dst)
{
    const int et = blockIdx.y;
    int e = blockIdx.x * blockDim.x + threadIdx.x;
    if (e >= EE) return;
    atomicAdd(&g_deg[et][dst[(long)et * EE + e]], 1);
}

__global__ __launch_bounds__(1024) void scan_kernel()
{
    const int et = blockIdx.x;
    const int t = threadIdx.x;
    const int CH = (NNODE + 1023) / 1024;
    const int start = t * CH;

    int sum = 0;
    for (int i = 0; i < CH; ++i) {
        int idx = start + i;
        if (idx < NNODE) sum += g_deg[et][idx];
    }
    __shared__ int wsums[32];
    const int lane = t & 31, wid = t >> 5;
    int v = sum;
    #pragma unroll
    for (int o = 1; o < 32; o <<= 1) {
        int n = __shfl_up_sync(0xffffffffu, v, o);
        if (lane >= o) v += n;
    }
    if (lane == 31) wsums[wid] = v;
    __syncthreads();
    if (wid == 0) {
        int x = wsums[lane];
        #pragma unroll
        for (int o = 1; o < 32; o <<= 1) {
            int n = __shfl_up_sync(0xffffffffu, x, o);
            if (lane >= o) x += n;
        }
        wsums[lane] = x;
    }
    __syncthreads();
    int excl = v - sum + (wid > 0 ? wsums[wid - 1] : 0);

    int run = excl;
    for (int i = 0; i < CH; ++i) {
        int idx = start + i;
        if (idx < NNODE) {
            g_rows[et][idx] = run;
            g_cursor[et][idx] = run;
            run += g_deg[et][idx];
        }
    }
    if (t == 1023) g_rows[et][NNODE] = run;
}

__global__ void scatter_kernel(const int* __restrict__ src, const int* __restrict__ dst)
{
    const int et = blockIdx.y;
    int e = blockIdx.x * blockDim.x + threadIdx.x;
    if (e >= EE) return;
    int s = src[(long)et * EE + e];
    int d = dst[(long)et * EE + e];
    int pos = atomicAdd(&g_cursor[et][d], 1);
    g_esrc[et][pos] = s;
}

// ======================= 4. warp-per-dst aggregation (4-edge unrolled) ============
__device__ __forceinline__ float dot8(const float4& qa, const float4& qb,
                                      const float4& ka, const float4& kb) {
    return qa.x * ka.x + qa.y * ka.y + qa.z * ka.z + qa.w * ka.w
         + qb.x * kb.x + qb.y * kb.y + qb.z * kb.z + qb.w * kb.w;
}

__global__ __launch_bounds__(256) void agg_kernel(const float* __restrict__ mu)
{
    const int et = blockIdx.y;
    const int dt = 1 - et;
    const int warp = threadIdx.x >> 5;
    const int lane = threadIdx.x & 31;
    const int node = blockIdx.x * 8 + warp;
    if (node >= NNODE) return;

    const int r0 = g_rows[et][node];
    const int r1 = g_rows[et][node + 1];

    const int h = lane >> 2;
    const int base = lane * 8;
    const float muh = mu[et * 8 + h] * ATT_SCALE;

    float acc[8];
    #pragma unroll
    for (int j = 0; j < 8; ++j) acc[j] = 0.f;
    float wsum = 0.f;

    if (r0 < r1) {
        const float* qrow = g_QKV[dt] + (size_t)node * QKVW + base;
        const float4 qa = *(const float4*)qrow;
        const float4 qb = *(const float4*)(qrow + 4);
        const int* __restrict__ ep = g_esrc[et];
        const float* __restrict__ kvbase = g_QKV[et];

        int j = r0;
        for (; j + 3 < r1; j += 4) {
            int sidx[4];
            #pragma unroll
            for (int u = 0; u < 4; ++u) sidx[u] = ep[j + u];
            float4 ka[4], kb[4], va[4], vb[4];
            #pragma unroll
            for (int u = 0; u < 4; ++u) {
                const float* kr = kvbase + (size_t)sidx[u] * QKVW + 256 + base;
                ka[u] = *(const float4*)kr;
                kb[u] = *(const float4*)(kr + 4);
                va[u] = *(const float4*)(kr + 256);
                vb[u] = *(const float4*)(kr + 260);
            }
            float p[4];
            #pragma unroll
            for (int u = 0; u < 4; ++u) p[u] = dot8(qa, qb, ka[u], kb[u]);
            #pragma unroll
            for (int u = 0; u < 4; ++u) p[u] += __shfl_xor_sync(0xffffffffu, p[u], 1);
            #pragma unroll
            for (int u = 0; u < 4; ++u) p[u] += __shfl_xor_sync(0xffffffffu, p[u], 2);
            #pragma unroll
            for (int u = 0; u < 4; ++u) {
                float w = expf(p[u] * muh);
                wsum += w;
                acc[0] += w * va[u].x;  acc[1] += w * va[u].y;
                acc[2] += w * va[u].z;  acc[3] += w * va[u].w;
                acc[4] += w * vb[u].x;  acc[5] += w * vb[u].y;
                acc[6] += w * vb[u].z;  acc[7] += w * vb[u].w;
            }
        }
        for (; j < r1; ++j) {
            const int s0 = ep[j];
            const float* kr0 = kvbase + (size_t)s0 * QKVW + 256 + base;
            float4 ka0 = *(const float4*)kr0;
            float4 kb0 = *(const float4*)(kr0 + 4);
            float4 va0 = *(const float4*)(kr0 + 256);
            float4 vb0 = *(const float4*)(kr0 + 260);
            float p0 = dot8(qa, qb, ka0, kb0);
            p0 += __shfl_xor_sync(0xffffffffu, p0, 1);
            p0 += __shfl_xor_sync(0xffffffffu, p0, 2);
            float w0 = expf(p0 * muh);
            wsum += w0;
            acc[0] += w0 * va0.x;  acc[1] += w0 * va0.y;
            acc[2] += w0 * va0.z;  acc[3] += w0 * va0.w;
            acc[4] += w0 * vb0.x;  acc[5] += w0 * vb0.y;
            acc[6] += w0 * vb0.z;  acc[7] += w0 * vb0.w;
        }
    }

    const float inv = (wsum > 0.f) ? 1.f / wsum : 0.f;
    __nv_bfloat162 hh[4], ll[4];
    #pragma unroll
    for (int j = 0; j < 4; ++j) {
        float x0 = acc[2 * j] * inv, x1 = acc[2 * j + 1] * inv;
        __nv_bfloat16 h0 = __float2bfloat16(x0), h1 = __float2bfloat16(x1);
        __nv_bfloat16 l0 = __float2bfloat16(x0 - __bfloat162float(h0));
        __nv_bfloat16 l1 = __float2bfloat16(x1 - __bfloat162float(h1));
        hh[j] = __halves2bfloat162(h0, h1);
        ll[j] = __halves2bfloat162(l0, l1);
    }
    const size_t o = (size_t)node * DDIM + base;
    *(uint4*)(g_hbf_hi[dt] + o) = *(const uint4*)hh;
    *(uint4*)(g_hbf_lo[dt] + o) = *(const uint4*)ll;
}

// ======================= 5. split-bf16 HMMA GEMM (R4 proven version) =============
#define BM 128
#define BN 128
#define BK 64
#define LDS_STRIDE 72
#define AS_HI 0
#define AS_LO (AS_HI + BM * LDS_STRIDE * 2)
#define BS_HI (AS_LO + BM * LDS_STRIDE * 2)
#define BS_LO (BS_HI + BN * LDS_STRIDE * 2)
#define GEMM_SMEM (BS_LO + BN * LDS_STRIDE * 2)

__global__ __launch_bounds__(256) void hmma_gemm_kernel(
    const __nv_bfloat16* __restrict__ Ahi, const __nv_bfloat16* __restrict__ Alo, long strideA,
    const __nv_bfloat16* __restrict__ Bhi, const __nv_bfloat16* __restrict__ Blo, long strideB,
    const float* __restrict__ bias, long strideBias,
    float* __restrict__ C, long strideC,
    int M, int Ntot)
{
    extern __shared__ char smem[];
    const uint32_t sbase = smem_u32(smem);

    const int tid = threadIdx.x;
    const int wid = tid >> 5, lane = tid & 31;
    const int t = blockIdx.z;
    const int m0 = blockIdx.x * BM;
    const int n0 = blockIdx.y * BN;
    const int mw = (wid & 1) * 64;
    const int nw = (wid >> 1) * 32;

    Ahi += (size_t)t * strideA;  Alo += (size_t)t * strideA;
    Bhi += (size_t)t * strideB;  Blo += (size_t)t * strideB;
    bias += (size_t)t * strideBias;
    C += (size_t)t * strideC;

    float acc[4][4][4];
    #pragma unroll
    for (int i = 0; i < 4; ++i)
        #pragma unroll
        for (int j = 0; j < 4; ++j)
            #pragma unroll
            for (int r = 0; r < 4; ++r) acc[i][j][r] = 0.f;

    for (int kofs = 0; kofs < 256; kofs += BK) {
        __syncthreads();
        #pragma unroll
        for (int i = 0; i < 4; ++i) {
            int idx = tid + i * 256;
            int row = idx >> 3, c = (idx & 7) * 8;
            uint32_t soff = (uint32_t)(row * LDS_STRIDE + c) * 2;
            uint4 vh = make_uint4(0, 0, 0, 0), vl = make_uint4(0, 0, 0, 0);
            int gr = m0 + row;
            if (gr < M) {
                size_t s = (size_t)gr * 256 + kofs + c;
                vh = *(const uint4*)(Ahi + s);
                vl = *(const uint4*)(Alo + s);
            }
            *(uint4*)(smem + AS_HI + soff) = vh;
            *(uint4*)(smem + AS_LO + soff) = vl;
        }
        #pragma unroll
        for (int i = 0; i < 4; ++i) {
            int idx = tid + i * 256;
            int row = idx >> 3, c = (idx & 7) * 8;
            uint32_t soff = (uint32_t)(row * LDS_STRIDE + c) * 2;
            size_t s = (size_t)(n0 + row) * 256 + kofs + c;
            *(uint4*)(smem + BS_HI + soff) = *(const uint4*)(Bhi + s);
            *(uint4*)(smem + BS_LO + soff) = *(const uint4*)(Blo + s);
        }
        __syncthreads();

        #pragma unroll
        for (int kk = 0; kk < BK / 16; ++kk) {
            uint32_t a_hi[4][4], a_lo[4][4], b_hi[4][2], b_lo[4][2];
            #pragma unroll
            for (int i = 0; i < 4; ++i) {
                uint32_t off = (uint32_t)((mw + i * 16 + (lane & 15)) * LDS_STRIDE
                                          + kk * 16 + (lane >> 4) * 8) * 2;
                ldm_x4(a_hi[i], sbase + AS_HI + off);
                ldm_x4(a_lo[i], sbase + AS_LO + off);
            }
            #pragma unroll
            for (int j = 0; j < 4; ++j) {
                uint32_t off = (uint32_t)((nw + j * 8 + (lane & 7)) * LDS_STRIDE
                                          + kk * 16 + ((lane >> 3) & 1) * 8) * 2;
                ldm_x2(b_hi[j], sbase + BS_HI + off);
                ldm_x2(b_lo[j], sbase + BS_LO + off);
            }
            #pragma unroll
            for (int i = 0; i < 4; ++i)
                #pragma unroll
                for (int j = 0; j < 4; ++j) {
                    mma_bf16(acc[i][j], a_hi[i], b_hi[j]);
                    mma_bf16(acc[i][j], a_hi[i], b_lo[j]);
                    mma_bf16(acc[i][j], a_lo[i], b_hi[j]);
                }
        }
    }

    #pragma unroll
    for (int i = 0; i < 4; ++i) {
        int r0 = m0 + mw + i * 16 + (lane >> 2);
        int r1 = r0 + 8;
        #pragma unroll
        for (int j = 0; j < 4; ++j) {
            int col = n0 + nw + j * 8 + (lane & 3) * 2;
            float b0 = bias[col], b1 = bias[col + 1];
            if (r0 < M) {
                float2 o = make_float2(acc[i][j][0] + b0, acc[i][j][1] + b1);
                *(float2*)(C + (size_t)r0 * Ntot + col) = o;
            }
            if (r1 < M) {
                float2 o = make_float2(acc[i][j][2] + b0, acc[i][j][3] + b1);
                *(float2*)(C + (size_t)r1 * Ntot + col) = o;
            }
        }
    }
}

// ======================= 6. skip-mix + LayerNorm =================================
__global__ __launch_bounds__(256) void ln_kernel(
    const float* __restrict__ feats, const float* __restrict__ skip,
    const float* __restrict__ ln_w, const float* __restrict__ ln_b,
    float* __restrict__ out)
{
    long row = (long)blockIdx.x * 8 + (threadIdx.x >> 5);
    const int lane = threadIdx.x & 31;
    const int t = (int)(row / NNODE);
    const float alpha = 1.f / (1.f + expf(-skip[t]));
    const float beta = 1.f - alpha;

    const float* tr = (const float*)g_trans + row * DDIM + lane * 8;
    const float* ft = feats + row * DDIM + lane * 8;

    float v[8];
    float4 t0 = *(const float4*)(tr);
    float4 t1 = *(const float4*)(tr + 4);
    float4 f0 = *(const float4*)(ft);
    float4 f1 = *(const float4*)(ft + 4);
    v[0] = alpha * t0.x + beta * f0.x;  v[1] = alpha * t0.y + beta * f0.y;
    v[2] = alpha * t0.z + beta * f0.z;  v[3] = alpha * t0.w + beta * f0.w;
    v[4] = alpha * t1.x + beta * f1.x;  v[5] = alpha * t1.y + beta * f1.y;
    v[6] = alpha * t1.z + beta * f1.z;  v[7] = alpha * t1.w + beta * f1.w;

    float sum = 0.f, sq = 0.f;
    #pragma unroll
    for (int j = 0; j < 8; ++j) { sum += v[j]; sq += v[j] * v[j]; }
    #pragma unroll
    for (int o = 16; o > 0; o >>= 1) {
        sum += __shfl_xor_sync(0xffffffffu, sum, o);
        sq  += __shfl_xor_sync(0xffffffffu, sq, o);
    }
    const float mean = sum * (1.f / 256.f);
    const float var  = sq * (1.f / 256.f) - mean * mean;
    const float rstd = rsqrtf(var + 1e-5f);

    const int cbase = t * 256 + lane * 8;
    float* op = out + row * DDIM + lane * 8;
    float4 o0, o1;
    o0.x = (v[0] - mean) * rstd * ln_w[cbase + 0] + ln_b[cbase + 0];
    o0.y = (v[1] - mean) * rstd * ln_w[cbase + 1] + ln_b[cbase + 1];
    o0.z = (v[2] - mean) * rstd * ln_w[cbase + 2] + ln_b[cbase + 2];
    o0.w = (v[3] - mean) * rstd * ln_w[cbase + 3] + ln_b[cbase + 3];
    o1.x = (v[4] - mean) * rstd * ln_w[cbase + 4] + ln_b[cbase + 4];
    o1.y = (v[5] - mean) * rstd * ln_w[cbase + 5] + ln_b[cbase + 5];
    o1.z = (v[6] - mean) * rstd * ln_w[cbase + 6] + ln_b[cbase + 6];
    o1.w = (v[7] - mean) * rstd * ln_w[cbase + 7] + ln_b[cbase + 7];
    *(float4*)(op)     = o0;
    *(float4*)(op + 4) = o1;
}

// ======================= host launch =============================================
extern "C" void kernel_launch(void* const* d_in, const int* in_sizes, int n_in,
                              void* d_out, int out_size)
{
    const float* feats = (const float*)d_in[0];
    const float* Wk    = (const float*)d_in[1];
    const float* bk    = (const float*)d_in[2];
    const float* Wq    = (const float*)d_in[3];
    const float* bq    = (const float*)d_in[4];
    const float* Wv    = (const float*)d_in[5];
    const float* bv    = (const float*)d_in[6];
    const float* Wa    = (const float*)d_in[7];
    const float* ba    = (const float*)d_in[8];
    const float* ln_w  = (const float*)d_in[9];
    const float* ln_b  = (const float*)d_in[10];
    const float* skip  = (const float*)d_in[11];
    const float* mu    = (const float*)d_in[12];
    const float* w_att = (const float*)d_in[13];
    const float* w_msg = (const float*)d_in[14];
    const int*   src   = (const int*)d_in[15];
    const int*   dst   = (const int*)d_in[16];
    float* out = (float*)d_out;

    static cudaStream_t s2 = nullptr;
    static cudaEvent_t evF = nullptr, evJ = nullptr;
    static bool init_done = false;
    if (!init_done) {
        cudaFuncSetAttribute(hmma_gemm_kernel,
                             cudaFuncAttributeMaxDynamicSharedMemorySize, GEMM_SMEM);
        cudaStreamCreateWithFlags(&s2, cudaStreamNonBlocking);
        cudaEventCreateWithFlags(&evF, cudaEventDisableTiming);
        cudaEventCreateWithFlags(&evJ, cudaEventDisableTiming);
        init_done = true;
    }

    float *pbcat, *pQKV, *ptrans;
    __nv_bfloat16 *pWcH, *pWcL, *pWaH, *pWaL, *pfH, *pfL, *phH, *phL;
    cudaGetSymbolAddress((void**)&pbcat, g_bcat);
    cudaGetSymbolAddress((void**)&pQKV, g_QKV);
    cudaGetSymbolAddress((void**)&ptrans, g_trans);
    cudaGetSymbolAddress((void**)&pWcH, g_WcatT_hi);
    cudaGetSymbolAddress((void**)&pWcL, g_WcatT_lo);
    cudaGetSymbolAddress((void**)&pWaH, g_WaT_hi);
    cudaGetSymbolAddress((void**)&pWaL, g_WaT_lo);
    cudaGetSymbolAddress((void**)&pfH, g_fbf_hi);
    cudaGetSymbolAddress((void**)&pfL, g_fbf_lo);
    cudaGetSymbolAddress((void**)&phH, g_hbf_hi);
    cudaGetSymbolAddress((void**)&phL, g_hbf_lo);

    // ---- fork: CSR build on side stream (depends only on src/dst) ----
    cudaEventRecord(evF, 0);
    cudaStreamWaitEvent(s2, evF, 0);
    zerodeg_kernel<<<(2 * NNODE + 255) / 256, 256, 0, s2>>>();
    {
        dim3 grid((EE + 255) / 256, 2);
        hist_kernel<<<grid, 256, 0, s2>>>(dst);
    }
    scan_kernel<<<2, 1024, 0, s2>>>();
    {
        dim3 grid((EE + 255) / 256, 2);
        scatter_kernel<<<grid, 256, 0, s2>>>(src, dst);
    }
    cudaEventRecord(evJ, s2);

    // ---- main stream: prep -> conv -> QKV GEMM ----
    {
        dim3 grid(1024, 2);
        prep_kernel<<<grid, 256>>>(Wk, bk, Wq, bq, Wv, bv, Wa, w_att, w_msg);
    }
    {
        const long n4 = 2L * NNODE * DDIM / 4;
        convsplit_kernel<<<(int)((n4 + 255) / 256), 256>>>(feats, pfH, pfL, n4);
    }
    {
        dim3 grid((NNODE + BM - 1) / BM, QKVW / BN, 2);
        hmma_gemm_kernel<<<grid, 256, GEMM_SMEM>>>(
            pfH, pfL, (long)NNODE * DDIM,
            pWcH, pWcL, (long)QKVW * DDIM,
            pbcat, (long)QKVW,
            pQKV, (long)NNODE * QKVW,
            NNODE, QKVW);
    }

    // ---- join: agg needs both QKV and CSR ----
    cudaStreamWaitEvent(0, evJ, 0);
    {
        dim3 grid((NNODE + 7) / 8, 2);
        agg_kernel<<<grid, 256>>>(mu);
    }

    // ---- output projection + LN ----
    {
        dim3 grid((NNODE + BM - 1) / BM, DDIM / BN, 2);
        hmma_gemm_kernel<<<grid, 256, GEMM_SMEM>>>(
            phH, phL, (long)NNODE * DDIM,
            pWaH, pWaL, (long)DDIM * DDIM,
            ba, (long)DDIM,
            ptrans, (long)NNODE * DDIM,
            NNODE, DDIM);
    }
    ln_kernel<<<(2 * NNODE) / 8, 256>>>(feats, skip, ln_w, ln_b, out);
}

// round 7
// speedup vs baseline: 1.3560x; 1.3560x over previous
#include <cuda_runtime.h>
#include <cuda_bf16.h>
#include <math.h>
#include <stdint.h>

#define NNODE 50000
#define DDIM  256
#define HH    8
#define EE    500000
#define QKVW  768
#define ATT_SCALE 0.17677669529663687f  // 1/sqrt(32)

// ======================= device scratch ==========================================
__device__ float g_bcat[2][QKVW];
__device__ __nv_bfloat16 g_WcatT_hi[2][(size_t)QKVW * DDIM];  // [n][k], n = Q|K'|V'
__device__ __nv_bfloat16 g_WcatT_lo[2][(size_t)QKVW * DDIM];
__device__ __nv_bfloat16 g_WaT_hi[2][(size_t)DDIM * DDIM];
__device__ __nv_bfloat16 g_WaT_lo[2][(size_t)DDIM * DDIM];
__device__ __nv_bfloat16 g_fbf_hi[2][(size_t)NNODE * DDIM];
__device__ __nv_bfloat16 g_fbf_lo[2][(size_t)NNODE * DDIM];
__device__ __nv_bfloat16 g_hbf_hi[2][(size_t)NNODE * DDIM];
__device__ __nv_bfloat16 g_hbf_lo[2][(size_t)NNODE * DDIM];
__device__ float g_QKV[2][(size_t)NNODE * QKVW];  // fp32: Q(256)|K'(256)|V'(256)
__device__ float g_trans[2][(size_t)NNODE * DDIM];
// CSR-by-destination scratch
__device__ int g_deg[2][NNODE];
__device__ int g_rows[2][NNODE + 1];
__device__ int g_cursor[2][NNODE];
__device__ int g_esrc[2][EE];

// ======================= PTX helpers (base-target safe) ==========================
__device__ __forceinline__ uint32_t smem_u32(const void* p) {
    uint32_t a;
    asm("{ .reg .u64 t; cvta.to.shared.u64 t, %1; cvt.u32.u64 %0, t; }" : "=r"(a) : "l"(p));
    return a;
}
__device__ __forceinline__ void ldm_x4(uint32_t* r, uint32_t addr) {
    asm volatile("ldmatrix.sync.aligned.m8n8.x4.shared.b16 {%0,%1,%2,%3}, [%4];"
                 : "=r"(r[0]), "=r"(r[1]), "=r"(r[2]), "=r"(r[3]) : "r"(addr));
}
__device__ __forceinline__ void ldm_x2(uint32_t* r, uint32_t addr) {
    asm volatile("ldmatrix.sync.aligned.m8n8.x2.shared.b16 {%0,%1}, [%2];"
                 : "=r"(r[0]), "=r"(r[1]) : "r"(addr));
}
__device__ __forceinline__ void mma_bf16(float* c, const uint32_t* a, const uint32_t* b) {
    asm volatile("mma.sync.aligned.m16n8k16.row.col.f32.bf16.bf16.f32 "
                 "{%0,%1,%2,%3}, {%4,%5,%6,%7}, {%8,%9}, {%0,%1,%2,%3};"
                 : "+f"(c[0]), "+f"(c[1]), "+f"(c[2]), "+f"(c[3])
                 : "r"(a[0]), "r"(a[1]), "r"(a[2]), "r"(a[3]), "r"(b[0]), "r"(b[1]));
}

// ======================= 1. prep: fold + transpose + bf16 split ==================
__global__ __launch_bounds__(256) void prep_kernel(
    const float* __restrict__ Wk, const float* __restrict__ bk,
    const float* __restrict__ Wq, const float* __restrict__ bq,
    const float* __restrict__ Wv, const float* __restrict__ bv,
    const float* __restrict__ Wa,
    const float* __restrict__ w_att, const float* __restrict__ w_msg)
{
    const int t = blockIdx.y;
    const int n = blockIdx.x;
    const int k = threadIdx.x;

    float val;
    if (n < 768) {
        if (n < 256) {
            val = Wq[((size_t)t * 256 + k) * 256 + n];
        } else {
            const int j = (n - 256) & 255;
            const int h = j >> 5, jj = j & 31;
            const float* W = (n < 512) ? Wk : Wv;
            const float* wm = ((n < 512) ? w_att : w_msg) + ((size_t)(t * 8 + h)) * 1024 + jj;
            const float* wrow = W + ((size_t)t * 256 + k) * 256 + h * 32;
            float a = 0.f;
            #pragma unroll 8
            for (int i = 0; i < 32; ++i) a += wrow[i] * wm[i * 32];
            val = a;
        }
        __nv_bfloat16 hi = __float2bfloat16(val);
        __nv_bfloat16 lo = __float2bfloat16(val - __bfloat162float(hi));
        g_WcatT_hi[t][(size_t)n * 256 + k] = hi;
        g_WcatT_lo[t][(size_t)n * 256 + k] = lo;
        if (k == 0) {
            float b;
            if (n < 256) b = bq[t * 256 + n];
            else {
                const int j = (n - 256) & 255;
                const int h = j >> 5, jj = j & 31;
                const float* bb = (n < 512) ? bk : bv;
                const float* wm = ((n < 512) ? w_att : w_msg) + ((size_t)(t * 8 + h)) * 1024 + jj;
                float a = 0.f;
                #pragma unroll 8
                for (int i = 0; i < 32; ++i) a += bb[t * 256 + h * 32 + i] * wm[i * 32];
                b = a;
            }
            g_bcat[t][n] = b;
        }
    } else {
        const int nn = n - 768;
        val = Wa[((size_t)t * 256 + k) * 256 + nn];
        __nv_bfloat16 hi = __float2bfloat16(val);
        __nv_bfloat16 lo = __float2bfloat16(val - __bfloat162float(hi));
        g_WaT_hi[t][(size_t)nn * 256 + k] = hi;
        g_WaT_lo[t][(size_t)nn * 256 + k] = lo;
    }
}

// ======================= 2. fp32 -> bf16 hi/lo split =============================
__global__ void convsplit_kernel(const float* __restrict__ src,
                                 __nv_bfloat16* __restrict__ hi,
                                 __nv_bfloat16* __restrict__ lo, long n4)
{
    long i = (long)blockIdx.x * blockDim.x + threadIdx.x;
    if (i >= n4) return;
    float4 v = ((const float4*)src)[i];
    __nv_bfloat16 h0 = __float2bfloat16(v.x), h1 = __float2bfloat16(v.y);
    __nv_bfloat16 h2 = __float2bfloat16(v.z), h3 = __float2bfloat16(v.w);
    __nv_bfloat16 l0 = __float2bfloat16(v.x - __bfloat162float(h0));
    __nv_bfloat16 l1 = __float2bfloat16(v.y - __bfloat162float(h1));
    __nv_bfloat16 l2 = __float2bfloat16(v.z - __bfloat162float(h2));
    __nv_bfloat16 l3 = __float2bfloat16(v.w - __bfloat162float(h3));
    ((__nv_bfloat162*)hi)[i * 2]     = __halves2bfloat162(h0, h1);
    ((__nv_bfloat162*)hi)[i * 2 + 1] = __halves2bfloat162(h2, h3);
    ((__nv_bfloat162*)lo)[i * 2]     = __halves2bfloat162(l0, l1);
    ((__nv_bfloat162*)lo)[i * 2 + 1] = __halves2bfloat162(l2, l3);
}

// ======================= 3. CSR build ============================================
__global__ void zerodeg_kernel()
{
    int i = blockIdx.x * blockDim.x + threadIdx.x;
    if (i < 2 * NNODE) ((int*)g_deg)[i] = 0;
}

__global__ void hist_kernel(const int* __restrict__ dst)
{
    const int et = blockIdx.y;
    int e = blockIdx.x * blockDim.x + threadIdx.x;
    if (e >= EE) return;
    atomicAdd(&g_deg[et][dst[(long)et * EE + e]], 1);
}

__global__ __launch_bounds__(1024) void scan_kernel()
{
    const int et = blockIdx.x;
    const int t = threadIdx.x;
    const int CH = (NNODE + 1023) / 1024;
    const int start = t * CH;

    int sum = 0;
    for (int i = 0; i < CH; ++i) {
        int idx = start + i;
        if (idx < NNODE) sum += g_deg[et][idx];
    }
    __shared__ int wsums[32];
    const int lane = t & 31, wid = t >> 5;
    int v = sum;
    #pragma unroll
    for (int o = 1; o < 32; o <<= 1) {
        int n = __shfl_up_sync(0xffffffffu, v, o);
        if (lane >= o) v += n;
    }
    if (lane == 31) wsums[wid] = v;
    __syncthreads();
    if (wid == 0) {
        int x = wsums[lane];
        #pragma unroll
        for (int o = 1; o < 32; o <<= 1) {
            int n = __shfl_up_sync(0xffffffffu, x, o);
            if (lane >= o) x += n;
        }
        wsums[lane] = x;
    }
    __syncthreads();
    int excl = v - sum + (wid > 0 ? wsums[wid - 1] : 0);

    int run = excl;
    for (int i = 0; i < CH; ++i) {
        int idx = start + i;
        if (idx < NNODE) {
            g_rows[et][idx] = run;
            g_cursor[et][idx] = run;
            run += g_deg[et][idx];
        }
    }
    if (t == 1023) g_rows[et][NNODE] = run;
}

__global__ void scatter_kernel(const int* __restrict__ src, const int* __restrict__ dst)
{
    const int et = blockIdx.y;
    int e = blockIdx.x * blockDim.x + threadIdx.x;
    if (e >= EE) return;
    int s = src[(long)et * EE + e];
    int d = dst[(long)et * EE + e];
    int pos = atomicAdd(&g_cursor[et][d], 1);
    g_esrc[et][pos] = s;
}

// ======================= 4. warp-per-dst aggregation (4-edge unrolled) ============
__device__ __forceinline__ float dot8(const float4& qa, const float4& qb,
                                      const float4& ka, const float4& kb) {
    return qa.x * ka.x + qa.y * ka.y + qa.z * ka.z + qa.w * ka.w
         + qb.x * kb.x + qb.y * kb.y + qb.z * kb.z + qb.w * kb.w;
}

__global__ __launch_bounds__(256) void agg_kernel(const float* __restrict__ mu)
{
    const int et = blockIdx.y;
    const int dt = 1 - et;
    const int warp = threadIdx.x >> 5;
    const int lane = threadIdx.x & 31;
    const int node = blockIdx.x * 8 + warp;
    if (node >= NNODE) return;

    const int r0 = g_rows[et][node];
    const int r1 = g_rows[et][node + 1];

    const int h = lane >> 2;
    const int base = lane * 8;
    const float muh = mu[et * 8 + h] * ATT_SCALE;

    float acc[8];
    #pragma unroll
    for (int j = 0; j < 8; ++j) acc[j] = 0.f;
    float wsum = 0.f;

    if (r0 < r1) {
        const float* qrow = g_QKV[dt] + (size_t)node * QKVW + base;
        const float4 qa = *(const float4*)qrow;
        const float4 qb = *(const float4*)(qrow + 4);
        const int* __restrict__ ep = g_esrc[et];
        const float* __restrict__ kvbase = g_QKV[et];

        int j = r0;
        for (; j + 3 < r1; j += 4) {
            int sidx[4];
            #pragma unroll
            for (int u = 0; u < 4; ++u) sidx[u] = ep[j + u];
            float4 ka[4], kb[4], va[4], vb[4];
            #pragma unroll
            for (int u = 0; u < 4; ++u) {
                const float* kr = kvbase + (size_t)sidx[u] * QKVW + 256 + base;
                ka[u] = *(const float4*)kr;
                kb[u] = *(const float4*)(kr + 4);
                va[u] = *(const float4*)(kr + 256);
                vb[u] = *(const float4*)(kr + 260);
            }
            float p[4];
            #pragma unroll
            for (int u = 0; u < 4; ++u) p[u] = dot8(qa, qb, ka[u], kb[u]);
            #pragma unroll
            for (int u = 0; u < 4; ++u) p[u] += __shfl_xor_sync(0xffffffffu, p[u], 1);
            #pragma unroll
            for (int u = 0; u < 4; ++u) p[u] += __shfl_xor_sync(0xffffffffu, p[u], 2);
            #pragma unroll
            for (int u = 0; u < 4; ++u) {
                float w = expf(p[u] * muh);
                wsum += w;
                acc[0] += w * va[u].x;  acc[1] += w * va[u].y;
                acc[2] += w * va[u].z;  acc[3] += w * va[u].w;
                acc[4] += w * vb[u].x;  acc[5] += w * vb[u].y;
                acc[6] += w * vb[u].z;  acc[7] += w * vb[u].w;
            }
        }
        for (; j < r1; ++j) {
            const int s0 = ep[j];
            const float* kr0 = kvbase + (size_t)s0 * QKVW + 256 + base;
            float4 ka0 = *(const float4*)kr0;
            float4 kb0 = *(const float4*)(kr0 + 4);
            float4 va0 = *(const float4*)(kr0 + 256);
            float4 vb0 = *(const float4*)(kr0 + 260);
            float p0 = dot8(qa, qb, ka0, kb0);
            p0 += __shfl_xor_sync(0xffffffffu, p0, 1);
            p0 += __shfl_xor_sync(0xffffffffu, p0, 2);
            float w0 = expf(p0 * muh);
            wsum += w0;
            acc[0] += w0 * va0.x;  acc[1] += w0 * va0.y;
            acc[2] += w0 * va0.z;  acc[3] += w0 * va0.w;
            acc[4] += w0 * vb0.x;  acc[5] += w0 * vb0.y;
            acc[6] += w0 * vb0.z;  acc[7] += w0 * vb0.w;
        }
    }

    const float inv = (wsum > 0.f) ? 1.f / wsum : 0.f;
    __nv_bfloat162 hh[4], ll[4];
    #pragma unroll
    for (int j = 0; j < 4; ++j) {
        float x0 = acc[2 * j] * inv, x1 = acc[2 * j + 1] * inv;
        __nv_bfloat16 h0 = __float2bfloat16(x0), h1 = __float2bfloat16(x1);
        __nv_bfloat16 l0 = __float2bfloat16(x0 - __bfloat162float(h0));
        __nv_bfloat16 l1 = __float2bfloat16(x1 - __bfloat162float(h1));
        hh[j] = __halves2bfloat162(h0, h1);
        ll[j] = __halves2bfloat162(l0, l1);
    }
    const size_t o = (size_t)node * DDIM + base;
    *(uint4*)(g_hbf_hi[dt] + o) = *(const uint4*)hh;
    *(uint4*)(g_hbf_lo[dt] + o) = *(const uint4*)ll;
}

// ======================= 5. split-bf16 HMMA GEMM (R4 proven version) =============
#define BM 128
#define BN 128
#define BK 64
#define LDS_STRIDE 72
#define AS_HI 0
#define AS_LO (AS_HI + BM * LDS_STRIDE * 2)
#define BS_HI (AS_LO + BM * LDS_STRIDE * 2)
#define BS_LO (BS_HI + BN * LDS_STRIDE * 2)
#define GEMM_SMEM (BS_LO + BN * LDS_STRIDE * 2)

__global__ __launch_bounds__(256) void hmma_gemm_kernel(
    const __nv_bfloat16* __restrict__ Ahi, const __nv_bfloat16* __restrict__ Alo, long strideA,
    const __nv_bfloat16* __restrict__ Bhi, const __nv_bfloat16* __restrict__ Blo, long strideB,
    const float* __restrict__ bias, long strideBias,
    float* __restrict__ C, long strideC,
    int M, int Ntot)
{
    extern __shared__ char smem[];
    const uint32_t sbase = smem_u32(smem);

    const int tid = threadIdx.x;
    const int wid = tid >> 5, lane = tid & 31;
    const int t = blockIdx.z;
    const int m0 = blockIdx.x * BM;
    const int n0 = blockIdx.y * BN;
    const int mw = (wid & 1) * 64;
    const int nw = (wid >> 1) * 32;

    Ahi += (size_t)t * strideA;  Alo += (size_t)t * strideA;
    Bhi += (size_t)t * strideB;  Blo += (size_t)t * strideB;
    bias += (size_t)t * strideBias;
    C += (size_t)t * strideC;

    float acc[4][4][4];
    #pragma unroll
    for (int i = 0; i < 4; ++i)
        #pragma unroll
        for (int j = 0; j < 4; ++j)
            #pragma unroll
            for (int r = 0; r < 4; ++r) acc[i][j][r] = 0.f;

    for (int kofs = 0; kofs < 256; kofs += BK) {
        __syncthreads();
        #pragma unroll
        for (int i = 0; i < 4; ++i) {
            int idx = tid + i * 256;
            int row = idx >> 3, c = (idx & 7) * 8;
            uint32_t soff = (uint32_t)(row * LDS_STRIDE + c) * 2;
            uint4 vh = make_uint4(0, 0, 0, 0), vl = make_uint4(0, 0, 0, 0);
            int gr = m0 + row;
            if (gr < M) {
                size_t s = (size_t)gr * 256 + kofs + c;
                vh = *(const uint4*)(Ahi + s);
                vl = *(const uint4*)(Alo + s);
            }
            *(uint4*)(smem + AS_HI + soff) = vh;
            *(uint4*)(smem + AS_LO + soff) = vl;
        }
        #pragma unroll
        for (int i = 0; i < 4; ++i) {
            int idx = tid + i * 256;
            int row = idx >> 3, c = (idx & 7) * 8;
            uint32_t soff = (uint32_t)(row * LDS_STRIDE + c) * 2;
            size_t s = (size_t)(n0 + row) * 256 + kofs + c;
            *(uint4*)(smem + BS_HI + soff) = *(const uint4*)(Bhi + s);
            *(uint4*)(smem + BS_LO + soff) = *(const uint4*)(Blo + s);
        }
        __syncthreads();

        #pragma unroll
        for (int kk = 0; kk < BK / 16; ++kk) {
            uint32_t a_hi[4][4], a_lo[4][4], b_hi[4][2], b_lo[4][2];
            #pragma unroll
            for (int i = 0; i < 4; ++i) {
                uint32_t off = (uint32_t)((mw + i * 16 + (lane & 15)) * LDS_STRIDE
                                          + kk * 16 + (lane >> 4) * 8) * 2;
                ldm_x4(a_hi[i], sbase + AS_HI + off);
                ldm_x4(a_lo[i], sbase + AS_LO + off);
            }
            #pragma unroll
            for (int j = 0; j < 4; ++j) {
                uint32_t off = (uint32_t)((nw + j * 8 + (lane & 7)) * LDS_STRIDE
                                          + kk * 16 + ((lane >> 3) & 1) * 8) * 2;
                ldm_x2(b_hi[j], sbase + BS_HI + off);
                ldm_x2(b_lo[j], sbase + BS_LO + off);
            }
            #pragma unroll
            for (int i = 0; i < 4; ++i)
                #pragma unroll
                for (int j = 0; j < 4; ++j) {
                    mma_bf16(acc[i][j], a_hi[i], b_hi[j]);
                    mma_bf16(acc[i][j], a_hi[i], b_lo[j]);
                    mma_bf16(acc[i][j], a_lo[i], b_hi[j]);
                }
        }
    }

    #pragma unroll
    for (int i = 0; i < 4; ++i) {
        int r0 = m0 + mw + i * 16 + (lane >> 2);
        int r1 = r0 + 8;
        #pragma unroll
        for (int j = 0; j < 4; ++j) {
            int col = n0 + nw + j * 8 + (lane & 3) * 2;
            float b0 = bias[col], b1 = bias[col + 1];
            if (r0 < M) {
                float2 o = make_float2(acc[i][j][0] + b0, acc[i][j][1] + b1);
                *(float2*)(C + (size_t)r0 * Ntot + col) = o;
            }
            if (r1 < M) {
                float2 o = make_float2(acc[i][j][2] + b0, acc[i][j][3] + b1);
                *(float2*)(C + (size_t)r1 * Ntot + col) = o;
            }
        }
    }
}

// ======================= 6. skip-mix + LayerNorm =================================
__global__ __launch_bounds__(256) void ln_kernel(
    const float* __restrict__ feats, const float* __restrict__ skip,
    const float* __restrict__ ln_w, const float* __restrict__ ln_b,
    float* __restrict__ out)
{
    long row = (long)blockIdx.x * 8 + (threadIdx.x >> 5);
    const int lane = threadIdx.x & 31;
    const int t = (int)(row / NNODE);
    const float alpha = 1.f / (1.f + expf(-skip[t]));
    const float beta = 1.f - alpha;

    const float* tr = (const float*)g_trans + row * DDIM + lane * 8;
    const float* ft = feats + row * DDIM + lane * 8;

    float v[8];
    float4 t0 = *(const float4*)(tr);
    float4 t1 = *(const float4*)(tr + 4);
    float4 f0 = *(const float4*)(ft);
    float4 f1 = *(const float4*)(ft + 4);
    v[0] = alpha * t0.x + beta * f0.x;  v[1] = alpha * t0.y + beta * f0.y;
    v[2] = alpha * t0.z + beta * f0.z;  v[3] = alpha * t0.w + beta * f0.w;
    v[4] = alpha * t1.x + beta * f1.x;  v[5] = alpha * t1.y + beta * f1.y;
    v[6] = alpha * t1.z + beta * f1.z;  v[7] = alpha * t1.w + beta * f1.w;

    float sum = 0.f, sq = 0.f;
    #pragma unroll
    for (int j = 0; j < 8; ++j) { sum += v[j]; sq += v[j] * v[j]; }
    #pragma unroll
    for (int o = 16; o > 0; o >>= 1) {
        sum += __shfl_xor_sync(0xffffffffu, sum, o);
        sq  += __shfl_xor_sync(0xffffffffu, sq, o);
    }
    const float mean = sum * (1.f / 256.f);
    const float var  = sq * (1.f / 256.f) - mean * mean;
    const float rstd = rsqrtf(var + 1e-5f);

    const int cbase = t * 256 + lane * 8;
    float* op = out + row * DDIM + lane * 8;
    float4 o0, o1;
    o0.x = (v[0] - mean) * rstd * ln_w[cbase + 0] + ln_b[cbase + 0];
    o0.y = (v[1] - mean) * rstd * ln_w[cbase + 1] + ln_b[cbase + 1];
    o0.z = (v[2] - mean) * rstd * ln_w[cbase + 2] + ln_b[cbase + 2];
    o0.w = (v[3] - mean) * rstd * ln_w[cbase + 3] + ln_b[cbase + 3];
    o1.x = (v[4] - mean) * rstd * ln_w[cbase + 4] + ln_b[cbase + 4];
    o1.y = (v[5] - mean) * rstd * ln_w[cbase + 5] + ln_b[cbase + 5];
    o1.z = (v[6] - mean) * rstd * ln_w[cbase + 6] + ln_b[cbase + 6];
    o1.w = (v[7] - mean) * rstd * ln_w[cbase + 7] + ln_b[cbase + 7];
    *(float4*)(op)     = o0;
    *(float4*)(op + 4) = o1;
}

// ======================= host launch =============================================
extern "C" void kernel_launch(void* const* d_in, const int* in_sizes, int n_in,
                              void* d_out, int out_size)
{
    const float* feats = (const float*)d_in[0];
    const float* Wk    = (const float*)d_in[1];
    const float* bk    = (const float*)d_in[2];
    const float* Wq    = (const float*)d_in[3];
    const float* bq    = (const float*)d_in[4];
    const float* Wv    = (const float*)d_in[5];
    const float* bv    = (const float*)d_in[6];
    const float* Wa    = (const float*)d_in[7];
    const float* ba    = (const float*)d_in[8];
    const float* ln_w  = (const float*)d_in[9];
    const float* ln_b  = (const float*)d_in[10];
    const float* skip  = (const float*)d_in[11];
    const float* mu    = (const float*)d_in[12];
    const float* w_att = (const float*)d_in[13];
    const float* w_msg = (const float*)d_in[14];
    const int*   src   = (const int*)d_in[15];
    const int*   dst   = (const int*)d_in[16];
    float* out = (float*)d_out;

    static bool attr_done = false;
    if (!attr_done) {
        cudaFuncSetAttribute(hmma_gemm_kernel,
                             cudaFuncAttributeMaxDynamicSharedMemorySize, GEMM_SMEM);
        attr_done = true;
    }

    float *pbcat, *pQKV, *ptrans;
    __nv_bfloat16 *pWcH, *pWcL, *pWaH, *pWaL, *pfH, *pfL, *phH, *phL;
    cudaGetSymbolAddress((void**)&pbcat, g_bcat);
    cudaGetSymbolAddress((void**)&pQKV, g_QKV);
    cudaGetSymbolAddress((void**)&ptrans, g_trans);
    cudaGetSymbolAddress((void**)&pWcH, g_WcatT_hi);
    cudaGetSymbolAddress((void**)&pWcL, g_WcatT_lo);
    cudaGetSymbolAddress((void**)&pWaH, g_WaT_hi);
    cudaGetSymbolAddress((void**)&pWaL, g_WaT_lo);
    cudaGetSymbolAddress((void**)&pfH, g_fbf_hi);
    cudaGetSymbolAddress((void**)&pfL, g_fbf_lo);
    cudaGetSymbolAddress((void**)&phH, g_hbf_hi);
    cudaGetSymbolAddress((void**)&phL, g_hbf_lo);

    // 1. weight prep
    {
        dim3 grid(1024, 2);
        prep_kernel<<<grid, 256>>>(Wk, bk, Wq, bq, Wv, bv, Wa, w_att, w_msg);
    }

    // 2. feats -> bf16 hi/lo
    {
        const long n4 = 2L * NNODE * DDIM / 4;
        convsplit_kernel<<<(int)((n4 + 255) / 256), 256>>>(feats, pfH, pfL, n4);
    }

    // 3. CSR build
    zerodeg_kernel<<<(2 * NNODE + 255) / 256, 256>>>();
    {
        dim3 grid((EE + 255) / 256, 2);
        hist_kernel<<<grid, 256>>>(dst);
    }
    scan_kernel<<<2, 1024>>>();
    {
        dim3 grid((EE + 255) / 256, 2);
        scatter_kernel<<<grid, 256>>>(src, dst);
    }

    // 4. QKV projection (HMMA)
    {
        dim3 grid((NNODE + BM - 1) / BM, QKVW / BN, 2);
        hmma_gemm_kernel<<<grid, 256, GEMM_SMEM>>>(
            pfH, pfL, (long)NNODE * DDIM,
            pWcH, pWcL, (long)QKVW * DDIM,
            pbcat, (long)QKVW,
            pQKV, (long)NNODE * QKVW,
            NNODE, QKVW);
    }

    // 5. aggregation
    {
        dim3 grid((NNODE + 7) / 8, 2);
        agg_kernel<<<grid, 256>>>(mu);
    }

    // 6. output projection (HMMA)
    {
        dim3 grid((NNODE + BM - 1) / BM, DDIM / BN, 2);
        hmma_gemm_kernel<<<grid, 256, GEMM_SMEM>>>(
            phH, phL, (long)NNODE * DDIM,
            pWaH, pWaL, (long)DDIM * DDIM,
            ba, (long)DDIM,
            ptrans, (long)NNODE * DDIM,
            NNODE, DDIM);
    }

    // 7. skip-mix + LayerNorm -> d_out
    ln_kernel<<<(2 * NNODE) / 8, 256>>>(feats, skip, ln_w, ln_b, out);
}